// round 8
// baseline (speedup 1.0000x reference)
#include <cuda_runtime.h>
#include <cstdint>

#define BD 4
#define CD 256
#define HD 56
#define WD 56
#define GD 16
#define GCD 16
#define POSN (BD*HD*WD)
#define IN1 2112
#define OUT1 96
#define OWD 112

#define BLKW 28          // positions (w) per block
#define KPG  136         // padded K per group (132 real)
#define DSTR 36          // D smem row stride (floats)
#define WSTR 100         // W smem row stride (floats)

// smem layout (float offsets)
#define S_TAPS 0                     // 16*9*30 = 4320
#define S_D    4320                  // 136*36  = 4896
#define S_W    9216                  // 136*100 = 13600
#define S_RS   22816                 // 28*97   = 2716
#define S_WA   25532                 // 28*100  = 2800
#define S_WB   28332                 // 2800
#define S_SMS  31132                 // 28*37   = 1036
#define S_TOT  32168                 // floats => 128672 bytes
#define S_W2S  0                     // overlay: 96*100 = 9600 (over TAPS+D)
#define S_W3S  9600                  //          96*100 (over D+W)
#define SMEM_BYTES (S_TOT * 4)

// Pre-transposed w1: [g][k][n], k in [0,136), zero for k>=132   (~835 KB, L2-resident)
__device__ float g_w1t[(size_t)GD * KPG * OUT1];

// ---------------------------------------------------------------------------
// Pre-kernel: transpose w1[n][col] -> g_w1t[g][k][n] with per-group K packing.
//   k <  36 : x1 features, col = g*36 + k
//   k <  84 : x2 features, col = 576  + g*48 + (k-36)
//   k < 132 : x3 features, col = 1344 + g*48 + (k-84)
// ---------------------------------------------------------------------------
__global__ __launch_bounds__(256) void w1t_kernel(const float* __restrict__ w1) {
    int idx = blockIdx.x * 256 + threadIdx.x;
    if (idx >= GD * KPG * OUT1) return;
    int n = idx % OUT1;
    int k = (idx / OUT1) % KPG;
    int g = idx / (OUT1 * KPG);
    float v = 0.f;
    if (k < 132) {
        int col;
        if (k < 36)      col = g*36 + k;
        else if (k < 84) col = 576  + g*48 + (k - 36);
        else             col = 1344 + g*48 + (k - 84);
        v = w1[(unsigned)n * IN1 + col];
    }
    g_w1t[idx] = v;
}

// ---------------------------------------------------------------------------
// TF32 helpers (3xTF32 split, verified in R6/R7)
// ---------------------------------------------------------------------------
__device__ __forceinline__ uint32_t f2tf32(float f) {
    uint32_t r;
    asm("cvt.rna.tf32.f32 %0, %1;" : "=r"(r) : "f"(f));
    return r;
}
__device__ __forceinline__ void mma_tf32(float* c, const uint32_t* a, const uint32_t* b) {
    asm volatile(
        "mma.sync.aligned.m16n8k8.row.col.f32.tf32.tf32.f32 "
        "{%0,%1,%2,%3}, {%4,%5,%6,%7}, {%8,%9}, {%0,%1,%2,%3};"
        : "+f"(c[0]), "+f"(c[1]), "+f"(c[2]), "+f"(c[3])
        : "r"(a[0]), "r"(a[1]), "r"(a[2]), "r"(a[3]), "r"(b[0]), "r"(b[1]));
}

// ---------------------------------------------------------------------------
// Fused kernel: block = (wsel, h2, b), 256 threads, ~126 KB dynamic smem.
// Scrambled-unfold taps: for output (h2, w2), tap (kh,kw):
//   m = kw*56 + h2;  h = m/3;  j = m%3;  T = x[b, c, h+kh-1, w2+j-1] (0 pad)
// taps smem: taps[(gc*9 + kw*3 + kh)*30 + p] = x[..., h(kw)+kh-1, w0+p-1]
// tap value for local wl: taps[.. + wl + jv[kw]],  jv[kw] = (kw*56+h2)%3
// ---------------------------------------------------------------------------
__global__ __launch_bounds__(256) void fused_kernel(
    const float* __restrict__ x,
    const float* __restrict__ gamma, const float* __restrict__ beta,
    const float* __restrict__ mean,  const float* __restrict__ var,
    const float* __restrict__ w2, const float* __restrict__ b2,
    const float* __restrict__ w3, const float* __restrict__ b3,
    float* __restrict__ out)
{
    extern __shared__ float sm[];
    const int wsel = blockIdx.x, h2 = blockIdx.y, b = blockIdx.z;
    const int w0 = wsel * BLKW;
    const int tid  = threadIdx.x;
    const int warp = tid >> 5, lane = tid & 31;
    const int wm = warp >> 2;          // 0..1 (m)
    const int wn = warp & 3;           // 0..3 (n)
    const int ar = lane >> 2, ac = lane & 3;

    const int jv0 = h2 % 3, jv1 = (56 + h2) % 3, jv2 = (112 + h2) % 3;

    // zero D (covers m-pad cols 28..35 and k-pad rows 132..135 forever)
    for (int i = tid; i < KPG * DSTR; i += 256) sm[S_D + i] = 0.f;

    float c[3][4];
    #pragma unroll
    for (int nt = 0; nt < 3; nt++)
        #pragma unroll
        for (int q = 0; q < 4; q++) c[nt][q] = 0.f;

    __syncthreads();

    // ================= Phase A: per-group descriptor + MMA accumulate ======
    for (int g = 0; g < GD; g++) {
        // --- taps load (16 gc x 9 taps x 30 cols) ---
        const unsigned cbase = (unsigned)(b*CD + g*GCD);
        for (int idx = tid; idx < GCD*9*30; idx += 256) {
            int p  = idx % 30;
            int t  = idx / 30;               // gc*9 + kw*3 + kh
            int kh = t % 3;
            int kw = (t / 3) % 3;
            int m  = kw*56 + h2;
            int hh = m/3 + kh - 1;
            int ww = w0 + p - 1;
            float v = 0.f;
            if (hh >= 0 && hh < HD && ww >= 0 && ww < WD)
                v = x[((cbase + (unsigned)(t/9))*HD + hh)*WD + ww];
            sm[S_TAPS + t*30 + p] = v;
        }
        __syncthreads();

        // --- D compute (132 x 28) + W tile load (coalesced) ---
        for (int idx = tid; idx < 132*BLKW; idx += 256) {
            int wl = idx % BLKW;
            int k  = idx / BLKW;
            float v;
            if (k < 36) {                   // x1: max over channels {jc,+4,+8,+12}
                int jc = k/9, r = k%9, kh = r/3, kw = r%3;
                int jvv = (kw==0) ? jv0 : (kw==1 ? jv1 : jv2);
                int base = S_TAPS + (jc*9 + kw*3 + kh)*30 + wl + jvv;
                v = fmaxf(fmaxf(sm[base], sm[base+1080]),
                          fmaxf(sm[base+2160], sm[base+3240]));
            } else if (k < 84) {            // x2: max over kh
                int kk = k - 36; int gc = kk/3, kw = kk%3;
                int jvv = (kw==0) ? jv0 : (kw==1 ? jv1 : jv2);
                int base = S_TAPS + (gc*9 + kw*3)*30 + wl + jvv;
                v = fmaxf(fmaxf(sm[base], sm[base+30]), sm[base+60]);
            } else {                        // x3: max over kw
                int kk = k - 84; int gc = kk/3, kh = kk%3;
                int t0 = S_TAPS + (gc*9 + kh)*30 + wl;
                v = fmaxf(fmaxf(sm[t0 + jv0], sm[t0 + 90 + jv1]),
                          sm[t0 + 180 + jv2]);
            }
            sm[S_D + k*DSTR + wl] = v;
        }
        for (int idx = tid; idx < KPG*OUT1; idx += 256) {
            int n = idx % OUT1, k = idx / OUT1;
            sm[S_W + k*WSTR + n] = g_w1t[(unsigned)(g*KPG + k)*OUT1 + idx % OUT1];
        }
        __syncthreads();

        // --- MMA: C[28x96] += D^T[28x136] @ W[136x96], 3xTF32 split ---
        #pragma unroll
        for (int kb = 0; kb < KPG; kb += 8) {
            const int mrow = wm*16 + ar;
            float a0 = sm[S_D + (kb+ac  )*DSTR + mrow];
            float a1 = sm[S_D + (kb+ac  )*DSTR + mrow + 8];
            float a2 = sm[S_D + (kb+ac+4)*DSTR + mrow];
            float a3 = sm[S_D + (kb+ac+4)*DSTR + mrow + 8];
            uint32_t ah[4], al[4];
            ah[0]=f2tf32(a0); al[0]=f2tf32(a0-__uint_as_float(ah[0]));
            ah[1]=f2tf32(a1); al[1]=f2tf32(a1-__uint_as_float(ah[1]));
            ah[2]=f2tf32(a2); al[2]=f2tf32(a2-__uint_as_float(ah[2]));
            ah[3]=f2tf32(a3); al[3]=f2tf32(a3-__uint_as_float(ah[3]));
            #pragma unroll
            for (int nt = 0; nt < 3; nt++) {
                int n0 = wn*24 + nt*8 + ar;
                float bb0 = sm[S_W + (kb+ac  )*WSTR + n0];
                float bb1 = sm[S_W + (kb+ac+4)*WSTR + n0];
                uint32_t bh[2], bl[2];
                bh[0]=f2tf32(bb0); bl[0]=f2tf32(bb0-__uint_as_float(bh[0]));
                bh[1]=f2tf32(bb1); bl[1]=f2tf32(bb1-__uint_as_float(bh[1]));
                mma_tf32(c[nt], ah, bl);
                mma_tf32(c[nt], al, bh);
                mma_tf32(c[nt], ah, bh);
            }
        }
        __syncthreads();
    }

    // ================= Epilogue: BN + ReLU -> rs[28][97] ====================
    #pragma unroll
    for (int nt = 0; nt < 3; nt++) {
        int n0 = wn*24 + nt*8 + 2*ac;
        float s0  = gamma[n0  ] * rsqrtf(var[n0  ] + 1e-5f);
        float bb0 = beta[n0  ] - mean[n0  ] * s0;
        float s1  = gamma[n0+1] * rsqrtf(var[n0+1] + 1e-5f);
        float bb1 = beta[n0+1] - mean[n0+1] * s1;
        int m0 = wm*16 + ar;
        if (m0 < BLKW) {
            sm[S_RS + m0*97 + n0  ] = fmaxf(fmaf(c[nt][0], s0, bb0), 0.f);
            sm[S_RS + m0*97 + n0+1] = fmaxf(fmaf(c[nt][1], s1, bb1), 0.f);
        }
        if (m0 + 8 < BLKW) {
            sm[S_RS + (m0+8)*97 + n0  ] = fmaxf(fmaf(c[nt][2], s0, bb0), 0.f);
            sm[S_RS + (m0+8)*97 + n0+1] = fmaxf(fmaf(c[nt][3], s1, bb1), 0.f);
        }
    }
    __syncthreads();

    // ================= Phase B: wa/wb = w2@r+b2, w3@r+b3 (all 96 outputs) ==
    for (int idx = tid; idx < 96*96; idx += 256) {
        int j = idx % 96, n = idx / 96;
        sm[S_W2S + n*100 + j] = w2[(unsigned)n*OUT1 + j];
        sm[S_W3S + n*100 + j] = w3[(unsigned)n*OUT1 + j];
    }
    __syncthreads();
    for (int idx = tid; idx < 96*BLKW; idx += 256) {
        int wl = idx % BLKW;
        int n  = idx / BLKW;
        float a2 = b2[n], a3 = b3[n];
        #pragma unroll 8
        for (int j = 0; j < 96; j++) {
            float rv = sm[S_RS + wl*97 + j];
            a2 = fmaf(sm[S_W2S + n*100 + j], rv, a2);
            a3 = fmaf(sm[S_W3S + n*100 + j], rv, a3);
        }
        sm[S_WA + wl*100 + n] = a2;
        sm[S_WB + wl*100 + n] = a3;
    }
    __syncthreads();

    // ================= Phase C/D per group: softmax + apply + store ========
    for (int g = 0; g < GD; g++) {
        // softmax over kk=9 for each (wl, t); pre-divide by 9 (mean)
        for (int idx = tid; idx < BLKW*4; idx += 256) {
            int wl = idx >> 2, t = idx & 3;
            int nh = t >> 1, nw = t & 1;
            float e[9], mx = -1e30f;
            #pragma unroll
            for (int kk = 0; kk < 9; kk++) {
                int kh = kk/3, kw = kk%3;
                e[kk] = sm[S_WA + wl*100 + g*6 + kh*2 + nh]
                      * sm[S_WB + wl*100 + g*6 + kw*2 + nw];
                mx = fmaxf(mx, e[kk]);
            }
            float s = 0.f;
            #pragma unroll
            for (int kk = 0; kk < 9; kk++) { e[kk] = expf(e[kk] - mx); s += e[kk]; }
            float inv = 1.f / (s * 9.f);
            #pragma unroll
            for (int kk = 0; kk < 9; kk++) sm[S_SMS + wl*37 + t*9 + kk] = e[kk] * inv;
        }
        // reload taps for this group
        const unsigned cbase = (unsigned)(b*CD + g*GCD);
        for (int idx = tid; idx < GCD*9*30; idx += 256) {
            int p  = idx % 30;
            int t  = idx / 30;
            int kh = t % 3;
            int kw = (t / 3) % 3;
            int m  = kw*56 + h2;
            int hh = m/3 + kh - 1;
            int ww = w0 + p - 1;
            float v = 0.f;
            if (hh >= 0 && hh < HD && ww >= 0 && ww < WD)
                v = x[((cbase + (unsigned)(t/9))*HD + hh)*WD + ww];
            sm[S_TAPS + t*30 + p] = v;
        }
        __syncthreads();

        // apply + interleaved store
        for (int idx = tid; idx < GCD*BLKW; idx += 256) {
            int wl = idx % BLKW;
            int gc = idx / BLKW;
            float o[4] = {0.f, 0.f, 0.f, 0.f};
            #pragma unroll
            for (int kk = 0; kk < 9; kk++) {
                int kh = kk/3, kw = kk%3;
                int jvv = (kw==0) ? jv0 : (kw==1 ? jv1 : jv2);
                float u = sm[S_TAPS + (gc*9 + kw*3 + kh)*30 + wl + jvv];
                #pragma unroll
                for (int t = 0; t < 4; t++)
                    o[t] = fmaf(u, sm[S_SMS + wl*37 + t*9 + kk], o[t]);
            }
            unsigned ch = (unsigned)(b*CD + g*GCD + gc);
            #pragma unroll
            for (int t = 0; t < 4; t++) {
                int nh = t >> 1, nw = t & 1;
                out[(ch*OWD + 2*h2 + nh)*OWD + 2*(w0 + wl) + nw] = o[t];
            }
        }
        __syncthreads();
    }
}

// ---------------------------------------------------------------------------
extern "C" void kernel_launch(void* const* d_in, const int* in_sizes, int n_in,
                              void* d_out, int out_size) {
    const float* x     = (const float*)d_in[0];
    const float* w1    = (const float*)d_in[1];
    const float* gamma = (const float*)d_in[2];
    const float* beta  = (const float*)d_in[3];
    const float* mean  = (const float*)d_in[4];
    const float* var   = (const float*)d_in[5];
    const float* w2    = (const float*)d_in[6];
    const float* b2    = (const float*)d_in[7];
    const float* w3    = (const float*)d_in[8];
    const float* b3    = (const float*)d_in[9];
    float* out = (float*)d_out;

    static bool attr_set = false;
    if (!attr_set) {
        cudaFuncSetAttribute(fused_kernel,
                             cudaFuncAttributeMaxDynamicSharedMemorySize, SMEM_BYTES);
        attr_set = true;
    }

    w1t_kernel<<<(GD*KPG*OUT1 + 255)/256, 256>>>(w1);
    fused_kernel<<<dim3(2, HD, BD), 256, SMEM_BYTES>>>(
        x, gamma, beta, mean, var, w2, b2, w3, b3, out);
}

// round 9
// speedup vs baseline: 2.2670x; 2.2670x over previous
#include <cuda_runtime.h>
#include <cstdint>

#define BD 4
#define CD 256
#define HD 56
#define WD 56
#define GD 16
#define GCD 16
#define POSN (BD*HD*WD)   // 12544
#define IN1 2112
#define OUT1 96
#define OWD 112
#define KHALF 1056        // IN1/2

// Scratch (device globals: no cudaMalloc allowed)
__device__ float g_desc[(size_t)IN1 * POSN];        // [feature][pos] ~106 MB (L2-resident)
__device__ float g_rp[2ull * POSN * OUT1];          // split-K partial sums, no BN yet
__device__ float g_w1h[(size_t)IN1 * OUT1];         // tf32-hi of w1^T, [k][n]
__device__ float g_w1l[(size_t)IN1 * OUT1];         // tf32 residual-lo

// ---------------------------------------------------------------------------
// TF32 helpers (3xTF32 split — verified rel_err ~1.3e-5 in R6/R7)
// ---------------------------------------------------------------------------
__device__ __forceinline__ uint32_t f2tf32(float f) {
    uint32_t r;
    asm("cvt.rna.tf32.f32 %0, %1;" : "=r"(r) : "f"(f));
    return r;
}
__device__ __forceinline__ void mma_tf32(float* c, const uint32_t* a, const uint32_t* b) {
    asm volatile(
        "mma.sync.aligned.m16n8k8.row.col.f32.tf32.tf32.f32 "
        "{%0,%1,%2,%3}, {%4,%5,%6,%7}, {%8,%9}, {%0,%1,%2,%3};"
        : "+f"(c[0]), "+f"(c[1]), "+f"(c[2]), "+f"(c[3])
        : "r"(a[0]), "r"(a[1]), "r"(a[2]), "r"(a[3]), "r"(b[0]), "r"(b[1]));
}

// ---------------------------------------------------------------------------
// K0: pre-split w1 into tf32 hi/lo, transposed to [k][n] for coalesced loads.
// ---------------------------------------------------------------------------
__global__ __launch_bounds__(256) void w1split_kernel(const float* __restrict__ w1) {
    int idx = blockIdx.x * 256 + threadIdx.x;
    if (idx >= IN1 * OUT1) return;
    int n = idx % OUT1;
    int k = idx / OUT1;
    float v = w1[(unsigned)n * IN1 + k];
    float h = __uint_as_float(f2tf32(v));
    g_w1h[idx] = h;
    g_w1l[idx] = __uint_as_float(f2tf32(v - h));
}

// ---------------------------------------------------------------------------
// Scrambled-unfold tap semantics (matches the ACTUAL reference code):
//   for output pos (h2, w2), tap (kh, kw):
//     m = kw*56 + h2;  h = m/3;  j = m%3
//     T[gc][kh][kw] = x[b, c, h + kh - 1, w2 + j - 1]   (0 outside)
// ---------------------------------------------------------------------------
__device__ __forceinline__ void load_taps(const float* __restrict__ x,
                                          int b, int g, int h2,
                                          float (*xs)[3][3][58], int tid) {
    const unsigned cbase = (unsigned)(b*CD + g*GCD);
    for (int idx = tid; idx < GCD * 9 * 58; idx += 128) {
        int wp = idx % 58;
        int t  = idx / 58;
        int kh = t % 3;
        int kw = (t / 3) % 3;
        int gc = t / 9;
        int m  = kw * 56 + h2;
        int hh = m / 3 + kh - 1;
        int ww = wp - 1;
        float v = 0.f;
        if (hh >= 0 && hh < HD && ww >= 0 && ww < WD)
            v = x[((cbase + gc)*HD + hh)*WD + ww];
        xs[gc][kw][kh][wp] = v;
    }
}

// ---------------------------------------------------------------------------
// K1: build descriptor  desc[feature][pos]   (unchanged, proven)
// ---------------------------------------------------------------------------
__global__ __launch_bounds__(128) void desc_kernel(const float* __restrict__ x) {
    const int g = blockIdx.x, h2 = blockIdx.y, b = blockIdx.z;
    __shared__ float xs[GCD][3][3][58];

    const int tid = threadIdx.x;
    load_taps(x, b, g, h2, xs, tid);
    __syncthreads();

    const int jv0 = h2 % 3, jv1 = (56 + h2) % 3, jv2 = (112 + h2) % 3;
    const unsigned posBase = (unsigned)(b*HD + h2)*WD;

    for (int it = tid; it < GCD * WD; it += 128) {
        int w  = it % WD;
        int gc = it / WD;
        float T[3][3];
        #pragma unroll
        for (int kh = 0; kh < 3; kh++) {
            T[kh][0] = xs[gc][0][kh][w + jv0];
            T[kh][1] = xs[gc][1][kh][w + jv1];
            T[kh][2] = xs[gc][2][kh][w + jv2];
        }
        unsigned f2 = (unsigned)(576 + g*48 + gc*3);
        unsigned f3 = (unsigned)(1344 + g*48 + gc*3);
        #pragma unroll
        for (int kw = 0; kw < 3; kw++) {
            float m = fmaxf(T[0][kw], fmaxf(T[1][kw], T[2][kw]));
            g_desc[(f2 + kw)*POSN + posBase + w] = m;
        }
        #pragma unroll
        for (int kh = 0; kh < 3; kh++) {
            float m = fmaxf(T[kh][0], fmaxf(T[kh][1], T[kh][2]));
            g_desc[(f3 + kh)*POSN + posBase + w] = m;
        }
    }

    const int jvv[3] = {jv0, jv1, jv2};
    for (int it = tid; it < 4 * WD; it += 128) {
        int w  = it % WD;
        int jc = it / WD;
        unsigned f1 = (unsigned)(g*36 + jc*9);
        #pragma unroll
        for (int kh = 0; kh < 3; kh++) {
            #pragma unroll
            for (int kw = 0; kw < 3; kw++) {
                int wp = w + jvv[kw];
                float m = xs[jc][kw][kh][wp];
                m = fmaxf(m, xs[jc + 4 ][kw][kh][wp]);
                m = fmaxf(m, xs[jc + 8 ][kw][kh][wp]);
                m = fmaxf(m, xs[jc + 12][kw][kh][wp]);
                g_desc[(f1 + kh*3 + kw)*POSN + posBase + w] = m;
            }
        }
    }
}

// ---------------------------------------------------------------------------
// K2: TC TF32 GEMM, BM=64, BN=96, BK=16, split-K=2 -> grid (196, 2).
// 256 threads = 8 warps as 2(m) x 4(n); warp tile 32m x 24n.
// B comes pre-split from g_w1h/g_w1l (no cvt in main loop).
// Stores PARTIAL sums (no BN/ReLU) to g_rp[khalf].
// ---------------------------------------------------------------------------
#define GBM 64
#define GBK 16
#define ASTR 72
#define BSTR 104

__global__ __launch_bounds__(256) void gemm_tc_kernel() {
    __shared__ float Ah[GBK][ASTR], Al[GBK][ASTR];   // 2 * 4608 B
    __shared__ float Bh[GBK][BSTR], Bl[GBK][BSTR];   // 2 * 6656 B

    const int tid  = threadIdx.x;
    const int warp = tid >> 5;
    const int lane = tid & 31;
    const int wm = warp >> 2;          // 0..1 (m)
    const int wn = warp & 3;           // 0..3 (n)
    const int ar = lane >> 2;          // 0..7
    const int ac = lane & 3;           // 0..3
    const unsigned row0 = blockIdx.x * GBM;
    const int khalf = blockIdx.y;
    const unsigned kbase = khalf * KHALF;

    float c[2][3][4];
    #pragma unroll
    for (int mt = 0; mt < 2; mt++)
        #pragma unroll
        for (int nt = 0; nt < 3; nt++)
            #pragma unroll
            for (int q = 0; q < 4; q++) c[mt][nt][q] = 0.f;

    const int am4 = tid & 15;          // A: 1 float4/thread
    const int ak  = tid >> 4;

    for (int k0 = 0; k0 < KHALF; k0 += GBK) {
        // A tile: 16k x 64m, split to tf32 hi/lo
        {
            float4 v = *reinterpret_cast<const float4*>(
                &g_desc[(kbase + k0 + ak)*POSN + row0 + am4*4]);
            float* dh = &Ah[ak][am4*4];
            float* dl = &Al[ak][am4*4];
            float h0 = __uint_as_float(f2tf32(v.x)); dh[0]=h0; dl[0]=__uint_as_float(f2tf32(v.x-h0));
            float h1 = __uint_as_float(f2tf32(v.y)); dh[1]=h1; dl[1]=__uint_as_float(f2tf32(v.y-h1));
            float h2 = __uint_as_float(f2tf32(v.z)); dh[2]=h2; dl[2]=__uint_as_float(f2tf32(v.z-h2));
            float h3 = __uint_as_float(f2tf32(v.w)); dh[3]=h3; dl[3]=__uint_as_float(f2tf32(v.w-h3));
        }
        // B tile: 16k x 96n from pre-split (coalesced, no cvt)
        {
            const unsigned base = (kbase + k0) * OUT1;
            #pragma unroll
            for (int i = 0; i < 6; i++) {
                int idx = tid + (i << 8);
                int n = idx % OUT1, k = idx / OUT1;
                Bh[k][n] = g_w1h[base + idx];
                Bl[k][n] = g_w1l[base + idx];
            }
        }
        __syncthreads();

        #pragma unroll
        for (int ks = 0; ks < 2; ks++) {
            const int kb = ks * 8;
            uint32_t ah[2][4], al[2][4];
            #pragma unroll
            for (int mt = 0; mt < 2; mt++) {
                int mrow = wm*32 + mt*16 + ar;
                ah[mt][0] = __float_as_uint(Ah[kb+ac  ][mrow  ]);
                ah[mt][1] = __float_as_uint(Ah[kb+ac  ][mrow+8]);
                ah[mt][2] = __float_as_uint(Ah[kb+ac+4][mrow  ]);
                ah[mt][3] = __float_as_uint(Ah[kb+ac+4][mrow+8]);
                al[mt][0] = __float_as_uint(Al[kb+ac  ][mrow  ]);
                al[mt][1] = __float_as_uint(Al[kb+ac  ][mrow+8]);
                al[mt][2] = __float_as_uint(Al[kb+ac+4][mrow  ]);
                al[mt][3] = __float_as_uint(Al[kb+ac+4][mrow+8]);
            }
            uint32_t bh[3][2], bl[3][2];
            #pragma unroll
            for (int nt = 0; nt < 3; nt++) {
                int n = wn*24 + nt*8 + ar;
                bh[nt][0] = __float_as_uint(Bh[kb+ac  ][n]);
                bh[nt][1] = __float_as_uint(Bh[kb+ac+4][n]);
                bl[nt][0] = __float_as_uint(Bl[kb+ac  ][n]);
                bl[nt][1] = __float_as_uint(Bl[kb+ac+4][n]);
            }
            #pragma unroll
            for (int mt = 0; mt < 2; mt++)
                #pragma unroll
                for (int nt = 0; nt < 3; nt++) {
                    mma_tf32(c[mt][nt], ah[mt], bl[nt]);
                    mma_tf32(c[mt][nt], al[mt], bh[nt]);
                    mma_tf32(c[mt][nt], ah[mt], bh[nt]);
                }
        }
        __syncthreads();
    }

    // Store partials (no BN — applied after the split-K sum, in apply_kernel)
    float* rp = &g_rp[(size_t)khalf * POSN * OUT1];
    #pragma unroll
    for (int nt = 0; nt < 3; nt++) {
        int n0 = wn*24 + nt*8 + 2*ac;
        #pragma unroll
        for (int mt = 0; mt < 2; mt++) {
            unsigned m0 = row0 + wm*32 + mt*16 + ar;
            *reinterpret_cast<float2*>(&rp[m0*OUT1 + n0]) =
                make_float2(c[mt][nt][0], c[mt][nt][1]);
            *reinterpret_cast<float2*>(&rp[(m0+8)*OUT1 + n0]) =
                make_float2(c[mt][nt][2], c[mt][nt][3]);
        }
    }
}

// ---------------------------------------------------------------------------
// K3: apply (R7 conflict-free layout). Phase 0 now: sum split-K partials,
// then BN + ReLU. wcs broadcast / rs stride-97 / sms stride-37 all
// conflict-free.
// ---------------------------------------------------------------------------
__global__ __launch_bounds__(128) void apply_kernel(
    const float* __restrict__ x,
    const float* __restrict__ gamma, const float* __restrict__ beta,
    const float* __restrict__ mean,  const float* __restrict__ var,
    const float* __restrict__ w2, const float* __restrict__ b2,
    const float* __restrict__ w3, const float* __restrict__ b3,
    float* __restrict__ out)
{
    const int g = blockIdx.x, h2 = blockIdx.y, b = blockIdx.z;
    __shared__ float bufA[GCD*3*3*58];      // 33408 B: rs then xs (union)
    __shared__ float wcs[12][96];           // 4608 B
    __shared__ float bcs[12];
    __shared__ float wab[WD][12];           // 2688 B
    __shared__ float sms[WD*37];            // 8288 B
    // total 49040 B < 48 KB

    float* rs = bufA;                                            // [WD][97]
    float (*xs)[3][3][58] = reinterpret_cast<float(*)[3][3][58]>(bufA);

    const int tid = threadIdx.x;
    const unsigned posBase = (unsigned)(b*HD + h2)*WD;

    // Phase 0: split-K sum + BN + ReLU -> rs
    for (int idx = tid; idx < WD * OUT1; idx += 128) {
        int w = idx / OUT1, j = idx % OUT1;
        float p = g_rp[posBase*OUT1 + idx]
                + g_rp[(size_t)POSN*OUT1 + posBase*OUT1 + idx];
        float s  = __ldg(&gamma[j]) * rsqrtf(__ldg(&var[j]) + 1e-5f);
        float bb = __ldg(&beta[j]) - __ldg(&mean[j]) * s;
        rs[w*97 + j] = fmaxf(fmaf(p, s, bb), 0.f);
    }
    for (int idx = tid; idx < 12 * 96; idx += 128) {
        int q = idx / 96, j = idx % 96;
        wcs[q][j] = (q < 6) ? w2[(g*6 + q)*OUT1 + j]
                            : w3[(g*6 + q - 6)*OUT1 + j];
    }
    if (tid < 12) {
        bcs[tid] = (tid < 6) ? b2[g*6 + tid] : b3[g*6 + tid - 6];
    }
    __syncthreads();

    // Phase 1: matvecs. w lane-fastest -> wcs broadcast, rs conflict-free.
    for (int it = tid; it < WD * 12; it += 128) {
        int w = it % WD;
        int q = it / WD;
        float acc = bcs[q];
        #pragma unroll 8
        for (int j = 0; j < 96; j++)
            acc = fmaf(wcs[q][j], rs[w*97 + j], acc);
        wab[w][q] = acc;
    }
    __syncthreads();   // rs dead; bufA reused as xs

    // Phase 2a: softmax over kk=9 per (w, nh, nw); pre-divide by 9
    for (int it = tid; it < WD * 4; it += 128) {
        int t = it % 4;
        int w = it / 4;
        int nh = t >> 1, nw = t & 1;
        float e[9], m = -1e30f;
        #pragma unroll
        for (int kk = 0; kk < 9; kk++) {
            int kh = kk / 3, kw = kk % 3;
            e[kk] = wab[w][kh*2 + nh] * wab[w][6 + kw*2 + nw];
            m = fmaxf(m, e[kk]);
        }
        float s = 0.f;
        #pragma unroll
        for (int kk = 0; kk < 9; kk++) { e[kk] = expf(e[kk] - m); s += e[kk]; }
        float inv = 1.f / (s * 9.f);
        #pragma unroll
        for (int kk = 0; kk < 9; kk++) sms[w*37 + t*9 + kk] = e[kk] * inv;
    }
    // Phase 2b: load scrambled taps into xs (overwrites rs)
    load_taps(x, b, g, h2, xs, tid);
    __syncthreads();

    const int jv0 = h2 % 3, jv1 = (56 + h2) % 3, jv2 = (112 + h2) % 3;
    const int jvv[3] = {jv0, jv1, jv2};

    // Phase 3: apply + interleaved store
    for (int it = tid; it < GCD * WD; it += 128) {
        int w  = it % WD;
        int gc = it / WD;
        float o[4] = {0.f, 0.f, 0.f, 0.f};
        #pragma unroll
        for (int kk = 0; kk < 9; kk++) {
            int kh = kk / 3, kw = kk % 3;
            float u = xs[gc][kw][kh][w + jvv[kw]];
            #pragma unroll
            for (int t = 0; t < 4; t++)
                o[t] = fmaf(u, sms[w*37 + t*9 + kk], o[t]);
        }
        int c = g*GCD + gc;
        #pragma unroll
        for (int t = 0; t < 4; t++) {
            int nh = t >> 1, nw = t & 1;
            out[(((unsigned)(b*CD + c))*OWD + 2*h2 + nh)*OWD + 2*w + nw] = o[t];
        }
    }
}

// ---------------------------------------------------------------------------
extern "C" void kernel_launch(void* const* d_in, const int* in_sizes, int n_in,
                              void* d_out, int out_size) {
    const float* x     = (const float*)d_in[0];
    const float* w1    = (const float*)d_in[1];
    const float* gamma = (const float*)d_in[2];
    const float* beta  = (const float*)d_in[3];
    const float* mean  = (const float*)d_in[4];
    const float* var   = (const float*)d_in[5];
    const float* w2    = (const float*)d_in[6];
    const float* b2    = (const float*)d_in[7];
    const float* w3    = (const float*)d_in[8];
    const float* b3    = (const float*)d_in[9];
    float* out = (float*)d_out;

    dim3 gridA(GD, HD, BD);   // (16, 56, 4)
    w1split_kernel<<<(IN1*OUT1 + 255)/256, 256>>>(w1);
    desc_kernel<<<gridA, 128>>>(x);
    gemm_tc_kernel<<<dim3(POSN / GBM, 2), 256>>>();
    apply_kernel<<<gridA, 128>>>(x, gamma, beta, mean, var, w2, b2, w3, b3, out);
}

// round 10
// speedup vs baseline: 2.5936x; 1.1441x over previous
#include <cuda_runtime.h>
#include <cstdint>

#define BD 4
#define CD 256
#define HD 56
#define WD 56
#define GD 16
#define GCD 16
#define POSN (BD*HD*WD)   // 12544
#define IN1 2112
#define OUT1 96
#define OWD 112
#define KHALF 1056        // IN1/2
#define N2 192            // w2|w3 concatenated outputs

// Scratch (device globals: no cudaMalloc allowed)
__device__ float g_desc[(size_t)IN1 * POSN];        // [feature][pos] ~106 MB
__device__ float g_rp[2ull * POSN * OUT1];          // split-K partials (pre-BN)
__device__ float g_w1h[(size_t)IN1 * OUT1];         // tf32-hi of w1^T [k][n]
__device__ float g_w1l[(size_t)IN1 * OUT1];
__device__ float g_w23h[(size_t)OUT1 * N2];         // tf32-hi of [w2|w3]^T [k][n]
__device__ float g_w23l[(size_t)OUT1 * N2];
__device__ float g_wab[(size_t)POSN * N2];          // wa (0..95) | wb (96..191)

// ---------------------------------------------------------------------------
// TF32 helpers (3xTF32 split)
// ---------------------------------------------------------------------------
__device__ __forceinline__ uint32_t f2tf32(float f) {
    uint32_t r;
    asm("cvt.rna.tf32.f32 %0, %1;" : "=r"(r) : "f"(f));
    return r;
}
__device__ __forceinline__ void mma_tf32(float* c, const uint32_t* a, const uint32_t* b) {
    asm volatile(
        "mma.sync.aligned.m16n8k8.row.col.f32.tf32.tf32.f32 "
        "{%0,%1,%2,%3}, {%4,%5,%6,%7}, {%8,%9}, {%0,%1,%2,%3};"
        : "+f"(c[0]), "+f"(c[1]), "+f"(c[2]), "+f"(c[3])
        : "r"(a[0]), "r"(a[1]), "r"(a[2]), "r"(a[3]), "r"(b[0]), "r"(b[1]));
}

// ---------------------------------------------------------------------------
// K0a: pre-split w1 -> [k][n] tf32 hi/lo
// ---------------------------------------------------------------------------
__global__ __launch_bounds__(256) void w1split_kernel(const float* __restrict__ w1) {
    int idx = blockIdx.x * 256 + threadIdx.x;
    if (idx >= IN1 * OUT1) return;
    int n = idx % OUT1;
    int k = idx / OUT1;
    float v = w1[(unsigned)n * IN1 + k];
    float h = __uint_as_float(f2tf32(v));
    g_w1h[idx] = h;
    g_w1l[idx] = __uint_as_float(f2tf32(v - h));
}

// ---------------------------------------------------------------------------
// K0b: pre-split [w2|w3] -> [k][n] tf32 hi/lo  (k<96, n<192)
// ---------------------------------------------------------------------------
__global__ __launch_bounds__(256) void w23split_kernel(
    const float* __restrict__ w2, const float* __restrict__ w3) {
    int idx = blockIdx.x * 256 + threadIdx.x;
    if (idx >= OUT1 * N2) return;
    int n = idx % N2;
    int k = idx / N2;
    float v = (n < OUT1) ? w2[(unsigned)n * OUT1 + k]
                         : w3[(unsigned)(n - OUT1) * OUT1 + k];
    float h = __uint_as_float(f2tf32(v));
    g_w23h[idx] = h;
    g_w23l[idx] = __uint_as_float(f2tf32(v - h));
}

// ---------------------------------------------------------------------------
// Scrambled-unfold taps (matches actual reference):
//   m = kw*56 + h2;  h = m/3;  j = m%3;  T = x[b,c,h+kh-1, w2+j-1] (0 pad)
// ---------------------------------------------------------------------------
__device__ __forceinline__ void load_taps(const float* __restrict__ x,
                                          int b, int g, int h2,
                                          float (*xs)[3][3][58], int tid) {
    const unsigned cbase = (unsigned)(b*CD + g*GCD);
    for (int idx = tid; idx < GCD * 9 * 58; idx += 128) {
        int wp = idx % 58;
        int t  = idx / 58;
        int kh = t % 3;
        int kw = (t / 3) % 3;
        int gc = t / 9;
        int m  = kw * 56 + h2;
        int hh = m / 3 + kh - 1;
        int ww = wp - 1;
        float v = 0.f;
        if (hh >= 0 && hh < HD && ww >= 0 && ww < WD)
            v = x[((cbase + gc)*HD + hh)*WD + ww];
        xs[gc][kw][kh][wp] = v;
    }
}

// ---------------------------------------------------------------------------
// K1: descriptor build (unchanged, proven)
// ---------------------------------------------------------------------------
__global__ __launch_bounds__(128) void desc_kernel(const float* __restrict__ x) {
    const int g = blockIdx.x, h2 = blockIdx.y, b = blockIdx.z;
    __shared__ float xs[GCD][3][3][58];

    const int tid = threadIdx.x;
    load_taps(x, b, g, h2, xs, tid);
    __syncthreads();

    const int jv0 = h2 % 3, jv1 = (56 + h2) % 3, jv2 = (112 + h2) % 3;
    const unsigned posBase = (unsigned)(b*HD + h2)*WD;

    for (int it = tid; it < GCD * WD; it += 128) {
        int w  = it % WD;
        int gc = it / WD;
        float T[3][3];
        #pragma unroll
        for (int kh = 0; kh < 3; kh++) {
            T[kh][0] = xs[gc][0][kh][w + jv0];
            T[kh][1] = xs[gc][1][kh][w + jv1];
            T[kh][2] = xs[gc][2][kh][w + jv2];
        }
        unsigned f2 = (unsigned)(576 + g*48 + gc*3);
        unsigned f3 = (unsigned)(1344 + g*48 + gc*3);
        #pragma unroll
        for (int kw = 0; kw < 3; kw++) {
            float m = fmaxf(T[0][kw], fmaxf(T[1][kw], T[2][kw]));
            g_desc[(f2 + kw)*POSN + posBase + w] = m;
        }
        #pragma unroll
        for (int kh = 0; kh < 3; kh++) {
            float m = fmaxf(T[kh][0], fmaxf(T[kh][1], T[kh][2]));
            g_desc[(f3 + kh)*POSN + posBase + w] = m;
        }
    }

    const int jvv[3] = {jv0, jv1, jv2};
    for (int it = tid; it < 4 * WD; it += 128) {
        int w  = it % WD;
        int jc = it / WD;
        unsigned f1 = (unsigned)(g*36 + jc*9);
        #pragma unroll
        for (int kh = 0; kh < 3; kh++) {
            #pragma unroll
            for (int kw = 0; kw < 3; kw++) {
                int wp = w + jvv[kw];
                float m = xs[jc][kw][kh][wp];
                m = fmaxf(m, xs[jc + 4 ][kw][kh][wp]);
                m = fmaxf(m, xs[jc + 8 ][kw][kh][wp]);
                m = fmaxf(m, xs[jc + 12][kw][kh][wp]);
                g_desc[(f1 + kh*3 + kw)*POSN + posBase + w] = m;
            }
        }
    }
}

// ---------------------------------------------------------------------------
// K2: GEMM1 (unchanged from R9): BM=64, split-K=2, grid (196,2), partials out
// ---------------------------------------------------------------------------
#define GBM 64
#define GBK 16
#define ASTR 72
#define BSTR 104

__global__ __launch_bounds__(256) void gemm_tc_kernel() {
    __shared__ float Ah[GBK][ASTR], Al[GBK][ASTR];
    __shared__ float Bh[GBK][BSTR], Bl[GBK][BSTR];

    const int tid  = threadIdx.x;
    const int warp = tid >> 5;
    const int lane = tid & 31;
    const int wm = warp >> 2;
    const int wn = warp & 3;
    const int ar = lane >> 2;
    const int ac = lane & 3;
    const unsigned row0 = blockIdx.x * GBM;
    const int khalf = blockIdx.y;
    const unsigned kbase = khalf * KHALF;

    float c[2][3][4];
    #pragma unroll
    for (int mt = 0; mt < 2; mt++)
        #pragma unroll
        for (int nt = 0; nt < 3; nt++)
            #pragma unroll
            for (int q = 0; q < 4; q++) c[mt][nt][q] = 0.f;

    const int am4 = tid & 15;
    const int ak  = tid >> 4;

    for (int k0 = 0; k0 < KHALF; k0 += GBK) {
        {
            float4 v = *reinterpret_cast<const float4*>(
                &g_desc[(kbase + k0 + ak)*POSN + row0 + am4*4]);
            float* dh = &Ah[ak][am4*4];
            float* dl = &Al[ak][am4*4];
            float h0 = __uint_as_float(f2tf32(v.x)); dh[0]=h0; dl[0]=__uint_as_float(f2tf32(v.x-h0));
            float h1 = __uint_as_float(f2tf32(v.y)); dh[1]=h1; dl[1]=__uint_as_float(f2tf32(v.y-h1));
            float h2 = __uint_as_float(f2tf32(v.z)); dh[2]=h2; dl[2]=__uint_as_float(f2tf32(v.z-h2));
            float h3 = __uint_as_float(f2tf32(v.w)); dh[3]=h3; dl[3]=__uint_as_float(f2tf32(v.w-h3));
        }
        {
            const unsigned base = (kbase + k0) * OUT1;
            #pragma unroll
            for (int i = 0; i < 6; i++) {
                int idx = tid + (i << 8);
                int n = idx % OUT1, k = idx / OUT1;
                Bh[k][n] = g_w1h[base + idx];
                Bl[k][n] = g_w1l[base + idx];
            }
        }
        __syncthreads();

        #pragma unroll
        for (int ks = 0; ks < 2; ks++) {
            const int kb = ks * 8;
            uint32_t ah[2][4], al[2][4];
            #pragma unroll
            for (int mt = 0; mt < 2; mt++) {
                int mrow = wm*32 + mt*16 + ar;
                ah[mt][0] = __float_as_uint(Ah[kb+ac  ][mrow  ]);
                ah[mt][1] = __float_as_uint(Ah[kb+ac  ][mrow+8]);
                ah[mt][2] = __float_as_uint(Ah[kb+ac+4][mrow  ]);
                ah[mt][3] = __float_as_uint(Ah[kb+ac+4][mrow+8]);
                al[mt][0] = __float_as_uint(Al[kb+ac  ][mrow  ]);
                al[mt][1] = __float_as_uint(Al[kb+ac  ][mrow+8]);
                al[mt][2] = __float_as_uint(Al[kb+ac+4][mrow  ]);
                al[mt][3] = __float_as_uint(Al[kb+ac+4][mrow+8]);
            }
            uint32_t bh[3][2], bl[3][2];
            #pragma unroll
            for (int nt = 0; nt < 3; nt++) {
                int n = wn*24 + nt*8 + ar;
                bh[nt][0] = __float_as_uint(Bh[kb+ac  ][n]);
                bh[nt][1] = __float_as_uint(Bh[kb+ac+4][n]);
                bl[nt][0] = __float_as_uint(Bl[kb+ac  ][n]);
                bl[nt][1] = __float_as_uint(Bl[kb+ac+4][n]);
            }
            #pragma unroll
            for (int mt = 0; mt < 2; mt++)
                #pragma unroll
                for (int nt = 0; nt < 3; nt++) {
                    mma_tf32(c[mt][nt], ah[mt], bl[nt]);
                    mma_tf32(c[mt][nt], al[mt], bh[nt]);
                    mma_tf32(c[mt][nt], ah[mt], bh[nt]);
                }
        }
        __syncthreads();
    }

    float* rp = &g_rp[(size_t)khalf * POSN * OUT1];
    #pragma unroll
    for (int nt = 0; nt < 3; nt++) {
        int n0 = wn*24 + nt*8 + 2*ac;
        #pragma unroll
        for (int mt = 0; mt < 2; mt++) {
            unsigned m0 = row0 + wm*32 + mt*16 + ar;
            *reinterpret_cast<float2*>(&rp[m0*OUT1 + n0]) =
                make_float2(c[mt][nt][0], c[mt][nt][1]);
            *reinterpret_cast<float2*>(&rp[(m0+8)*OUT1 + n0]) =
                make_float2(c[mt][nt][2], c[mt][nt][3]);
        }
    }
}

// ---------------------------------------------------------------------------
// K2b: GEMM2: g_wab[m][192] = relu(BN(rp0+rp1))[m][96] @ w23[96][192] + bias
// BM=64, BN=192, BK=16, 256 threads = 8 warps (2m x 4n), warp 32m x 48n.
// A-load fuses split-K sum + BN + ReLU + tf32 split.
// ---------------------------------------------------------------------------
#define A2STR 72
#define B2STR 200

__global__ __launch_bounds__(256) void gemm2_kernel(
    const float* __restrict__ gamma, const float* __restrict__ beta,
    const float* __restrict__ mean,  const float* __restrict__ var,
    const float* __restrict__ b2,    const float* __restrict__ b3)
{
    __shared__ float A2h[GBK][A2STR], A2l[GBK][A2STR];   // 2*4608 B
    __shared__ float B2h[GBK][B2STR], B2l[GBK][B2STR];   // 2*12800 B
    __shared__ float sS[OUT1], sB[OUT1];

    const int tid  = threadIdx.x;
    const int warp = tid >> 5;
    const int lane = tid & 31;
    const int wm = warp >> 2;
    const int wn = warp & 3;
    const int ar = lane >> 2;
    const int ac = lane & 3;
    const unsigned row0 = blockIdx.x * GBM;

    if (tid < OUT1) {
        float s = gamma[tid] * rsqrtf(var[tid] + 1e-5f);
        sS[tid] = s;
        sB[tid] = beta[tid] - mean[tid] * s;
    }
    __syncthreads();

    float c[2][6][4];
    #pragma unroll
    for (int mt = 0; mt < 2; mt++)
        #pragma unroll
        for (int nt = 0; nt < 6; nt++)
            #pragma unroll
            for (int q = 0; q < 4; q++) c[mt][nt][q] = 0.f;

    const int am = tid >> 2;          // 0..63
    const int akq = tid & 3;          // 0..3 -> k = akq*4..+3

    #pragma unroll
    for (int k0 = 0; k0 < OUT1; k0 += GBK) {
        // A tile: r computed on the fly from partials
        {
            int kk = k0 + akq*4;
            unsigned base = (row0 + am)*OUT1 + kk;
            float4 p0 = *reinterpret_cast<const float4*>(&g_rp[base]);
            float4 p1 = *reinterpret_cast<const float4*>(&g_rp[(size_t)POSN*OUT1 + base]);
            float v[4] = {p0.x+p1.x, p0.y+p1.y, p0.z+p1.z, p0.w+p1.w};
            #pragma unroll
            for (int i = 0; i < 4; i++) {
                float r = fmaxf(fmaf(v[i], sS[kk+i], sB[kk+i]), 0.f);
                float h = __uint_as_float(f2tf32(r));
                A2h[akq*4 + i][am] = h;
                A2l[akq*4 + i][am] = __uint_as_float(f2tf32(r - h));
            }
        }
        // B tile: 16k x 192n pre-split, coalesced
        {
            const unsigned base = (unsigned)k0 * N2;
            #pragma unroll
            for (int i = 0; i < 12; i++) {
                int idx = tid + (i << 8);
                int n = idx % N2, k = idx / N2;
                B2h[k][n] = g_w23h[base + idx];
                B2l[k][n] = g_w23l[base + idx];
            }
        }
        __syncthreads();

        #pragma unroll
        for (int ks = 0; ks < 2; ks++) {
            const int kb = ks * 8;
            uint32_t ah[2][4], al[2][4];
            #pragma unroll
            for (int mt = 0; mt < 2; mt++) {
                int mrow = wm*32 + mt*16 + ar;
                ah[mt][0] = __float_as_uint(A2h[kb+ac  ][mrow  ]);
                ah[mt][1] = __float_as_uint(A2h[kb+ac  ][mrow+8]);
                ah[mt][2] = __float_as_uint(A2h[kb+ac+4][mrow  ]);
                ah[mt][3] = __float_as_uint(A2h[kb+ac+4][mrow+8]);
                al[mt][0] = __float_as_uint(A2l[kb+ac  ][mrow  ]);
                al[mt][1] = __float_as_uint(A2l[kb+ac  ][mrow+8]);
                al[mt][2] = __float_as_uint(A2l[kb+ac+4][mrow  ]);
                al[mt][3] = __float_as_uint(A2l[kb+ac+4][mrow+8]);
            }
            uint32_t bh[6][2], bl[6][2];
            #pragma unroll
            for (int nt = 0; nt < 6; nt++) {
                int n = wn*48 + nt*8 + ar;
                bh[nt][0] = __float_as_uint(B2h[kb+ac  ][n]);
                bh[nt][1] = __float_as_uint(B2h[kb+ac+4][n]);
                bl[nt][0] = __float_as_uint(B2l[kb+ac  ][n]);
                bl[nt][1] = __float_as_uint(B2l[kb+ac+4][n]);
            }
            #pragma unroll
            for (int mt = 0; mt < 2; mt++)
                #pragma unroll
                for (int nt = 0; nt < 6; nt++) {
                    mma_tf32(c[mt][nt], ah[mt], bl[nt]);
                    mma_tf32(c[mt][nt], al[mt], bh[nt]);
                    mma_tf32(c[mt][nt], ah[mt], bh[nt]);
                }
        }
        __syncthreads();
    }

    // Epilogue: + bias (b2 for n<96, b3 for n>=96), store g_wab
    #pragma unroll
    for (int nt = 0; nt < 6; nt++) {
        int n0 = wn*48 + nt*8 + 2*ac;             // n0, n0+1 same side of 96
        float bias0 = (n0 < OUT1) ? b2[n0] : b3[n0 - OUT1];
        float bias1 = (n0 + 1 < OUT1) ? b2[n0 + 1] : b3[n0 + 1 - OUT1];
        #pragma unroll
        for (int mt = 0; mt < 2; mt++) {
            unsigned m0 = row0 + wm*32 + mt*16 + ar;
            *reinterpret_cast<float2*>(&g_wab[(size_t)m0*N2 + n0]) =
                make_float2(c[mt][nt][0] + bias0, c[mt][nt][1] + bias1);
            *reinterpret_cast<float2*>(&g_wab[(size_t)(m0+8)*N2 + n0]) =
                make_float2(c[mt][nt][2] + bias0, c[mt][nt][3] + bias1);
        }
    }
}

// ---------------------------------------------------------------------------
// K3: apply — now only taps + softmax + apply + store
// ---------------------------------------------------------------------------
__global__ __launch_bounds__(128) void apply_kernel(
    const float* __restrict__ x, float* __restrict__ out)
{
    const int g = blockIdx.x, h2 = blockIdx.y, b = blockIdx.z;
    __shared__ float xs[GCD][3][3][58];     // 33408 B
    __shared__ float wab[WD][12];           // 2688 B
    __shared__ float sms[WD*37];            // 8288 B

    const int tid = threadIdx.x;
    const unsigned posBase = (unsigned)(b*HD + h2)*WD;

    // Phase 0: wab slice (6+6 contiguous floats per pos) + taps
    for (int it = tid; it < WD * 12; it += 128) {
        int q = it % 12;
        int w = it / 12;
        int col = (q < 6) ? (g*6 + q) : (OUT1 + g*6 + q - 6);
        wab[w][q] = g_wab[(size_t)(posBase + w)*N2 + col];
    }
    load_taps(x, b, g, h2, xs, tid);
    __syncthreads();

    // Phase 1: softmax over kk=9 per (w, nh, nw); pre-divide by 9 (mean)
    for (int it = tid; it < WD * 4; it += 128) {
        int t = it % 4;
        int w = it / 4;
        int nh = t >> 1, nw = t & 1;
        float e[9], m = -1e30f;
        #pragma unroll
        for (int kk = 0; kk < 9; kk++) {
            int kh = kk / 3, kw = kk % 3;
            e[kk] = wab[w][kh*2 + nh] * wab[w][6 + kw*2 + nw];
            m = fmaxf(m, e[kk]);
        }
        float s = 0.f;
        #pragma unroll
        for (int kk = 0; kk < 9; kk++) { e[kk] = expf(e[kk] - m); s += e[kk]; }
        float inv = 1.f / (s * 9.f);
        #pragma unroll
        for (int kk = 0; kk < 9; kk++) sms[w*37 + t*9 + kk] = e[kk] * inv;
    }
    __syncthreads();

    const int jv0 = h2 % 3, jv1 = (56 + h2) % 3, jv2 = (112 + h2) % 3;
    const int jvv[3] = {jv0, jv1, jv2};

    // Phase 2: apply + interleaved store
    for (int it = tid; it < GCD * WD; it += 128) {
        int w  = it % WD;
        int gc = it / WD;
        float o[4] = {0.f, 0.f, 0.f, 0.f};
        #pragma unroll
        for (int kk = 0; kk < 9; kk++) {
            int kh = kk / 3, kw = kk % 3;
            float u = xs[gc][kw][kh][w + jvv[kw]];
            #pragma unroll
            for (int t = 0; t < 4; t++)
                o[t] = fmaf(u, sms[w*37 + t*9 + kk], o[t]);
        }
        int c = g*GCD + gc;
        #pragma unroll
        for (int t = 0; t < 4; t++) {
            int nh = t >> 1, nw = t & 1;
            out[(((unsigned)(b*CD + c))*OWD + 2*h2 + nh)*OWD + 2*w + nw] = o[t];
        }
    }
}

// ---------------------------------------------------------------------------
extern "C" void kernel_launch(void* const* d_in, const int* in_sizes, int n_in,
                              void* d_out, int out_size) {
    const float* x     = (const float*)d_in[0];
    const float* w1    = (const float*)d_in[1];
    const float* gamma = (const float*)d_in[2];
    const float* beta  = (const float*)d_in[3];
    const float* mean  = (const float*)d_in[4];
    const float* var   = (const float*)d_in[5];
    const float* w2    = (const float*)d_in[6];
    const float* b2    = (const float*)d_in[7];
    const float* w3    = (const float*)d_in[8];
    const float* b3    = (const float*)d_in[9];
    float* out = (float*)d_out;

    dim3 gridA(GD, HD, BD);   // (16, 56, 4)
    w1split_kernel<<<(IN1*OUT1 + 255)/256, 256>>>(w1);
    w23split_kernel<<<(OUT1*N2 + 255)/256, 256>>>(w2, w3);
    desc_kernel<<<gridA, 128>>>(x);
    gemm_tc_kernel<<<dim3(POSN / GBM, 2), 256>>>();
    gemm2_kernel<<<POSN / GBM, 256>>>(gamma, beta, mean, var, b2, b3);
    apply_kernel<<<gridA, 128>>>(x, out);
}

// round 11
// speedup vs baseline: 3.1651x; 1.2204x over previous
#include <cuda_runtime.h>
#include <cuda_bf16.h>
#include <cstdint>

#define BD 4
#define CD 256
#define HD 56
#define WD 56
#define GD 16
#define GCD 16
#define POSN (BD*HD*WD)   // 12544
#define IN1 2112
#define OUT1 96
#define OWD 112
#define KHALF 1056        // IN1/2 (k units)
#define N2 192

// Scratch (device globals)
__device__ float    g_desc[(size_t)IN1 * POSN];      // [feature][pos] ~106 MB
__device__ float    g_rp[2ull * POSN * OUT1];        // split-K partials (pre-BN)
__device__ uint32_t g_w1ph[(size_t)(IN1/2) * OUT1];  // bf16x2-packed hi, [kp][n]
__device__ uint32_t g_w1pl[(size_t)(IN1/2) * OUT1];  // bf16x2-packed lo residual
__device__ float    g_w23h[(size_t)OUT1 * N2];       // tf32 split for gemm2
__device__ float    g_w23l[(size_t)OUT1 * N2];
__device__ float    g_wab[(size_t)POSN * N2];        // wa | wb

// ---------------------------------------------------------------------------
// helpers
// ---------------------------------------------------------------------------
__device__ __forceinline__ uint32_t f2tf32(float f) {
    uint32_t r;
    asm("cvt.rna.tf32.f32 %0, %1;" : "=r"(r) : "f"(f));
    return r;
}
__device__ __forceinline__ void mma_tf32(float* c, const uint32_t* a, const uint32_t* b) {
    asm volatile(
        "mma.sync.aligned.m16n8k8.row.col.f32.tf32.tf32.f32 "
        "{%0,%1,%2,%3}, {%4,%5,%6,%7}, {%8,%9}, {%0,%1,%2,%3};"
        : "+f"(c[0]), "+f"(c[1]), "+f"(c[2]), "+f"(c[3])
        : "r"(a[0]), "r"(a[1]), "r"(a[2]), "r"(a[3]), "r"(b[0]), "r"(b[1]));
}
__device__ __forceinline__ void mma_bf16(float* c, const uint32_t* a, const uint32_t* b) {
    asm volatile(
        "mma.sync.aligned.m16n8k16.row.col.f32.bf16.bf16.f32 "
        "{%0,%1,%2,%3}, {%4,%5,%6,%7}, {%8,%9}, {%0,%1,%2,%3};"
        : "+f"(c[0]), "+f"(c[1]), "+f"(c[2]), "+f"(c[3])
        : "r"(a[0]), "r"(a[1]), "r"(a[2]), "r"(a[3]), "r"(b[0]), "r"(b[1]));
}
// pack k-pair: lo half = even k, hi half = odd k
__device__ __forceinline__ uint32_t packbf(float klo, float khi) {
    uint32_t r;
    asm("cvt.rn.bf16x2.f32 %0, %1, %2;" : "=r"(r) : "f"(khi), "f"(klo));
    return r;
}
__device__ __forceinline__ float bfround(float v) {
    return __bfloat162float(__float2bfloat16(v));
}

// ---------------------------------------------------------------------------
// K0a: pack w1 -> bf16x2 hi/lo, [kp][n]  (kp = k/2)
// ---------------------------------------------------------------------------
__global__ __launch_bounds__(256) void w1pack_kernel(const float* __restrict__ w1) {
    int idx = blockIdx.x * 256 + threadIdx.x;
    if (idx >= (IN1/2) * OUT1) return;
    int n  = idx % OUT1;
    int kp = idx / OUT1;
    float v0 = w1[(unsigned)n * IN1 + 2*kp];
    float v1 = w1[(unsigned)n * IN1 + 2*kp + 1];
    float h0 = bfround(v0), h1 = bfround(v1);
    g_w1ph[idx] = packbf(h0, h1);
    g_w1pl[idx] = packbf(v0 - h0, v1 - h1);
}

// ---------------------------------------------------------------------------
// K0b: pre-split [w2|w3] -> [k][n] tf32 hi/lo (gemm2, unchanged)
// ---------------------------------------------------------------------------
__global__ __launch_bounds__(256) void w23split_kernel(
    const float* __restrict__ w2, const float* __restrict__ w3) {
    int idx = blockIdx.x * 256 + threadIdx.x;
    if (idx >= OUT1 * N2) return;
    int n = idx % N2;
    int k = idx / N2;
    float v = (n < OUT1) ? w2[(unsigned)n * OUT1 + k]
                         : w3[(unsigned)(n - OUT1) * OUT1 + k];
    float h = __uint_as_float(f2tf32(v));
    g_w23h[idx] = h;
    g_w23l[idx] = __uint_as_float(f2tf32(v - h));
}

// ---------------------------------------------------------------------------
// Scrambled-unfold taps (matches actual reference)
// ---------------------------------------------------------------------------
__device__ __forceinline__ void load_taps(const float* __restrict__ x,
                                          int b, int g, int h2,
                                          float (*xs)[3][3][58], int tid) {
    const unsigned cbase = (unsigned)(b*CD + g*GCD);
    for (int idx = tid; idx < GCD * 9 * 58; idx += 128) {
        int wp = idx % 58;
        int t  = idx / 58;
        int kh = t % 3;
        int kw = (t / 3) % 3;
        int gc = t / 9;
        int m  = kw * 56 + h2;
        int hh = m / 3 + kh - 1;
        int ww = wp - 1;
        float v = 0.f;
        if (hh >= 0 && hh < HD && ww >= 0 && ww < WD)
            v = x[((cbase + gc)*HD + hh)*WD + ww];
        xs[gc][kw][kh][wp] = v;
    }
}

// ---------------------------------------------------------------------------
// K1: descriptor build (unchanged, proven)
// ---------------------------------------------------------------------------
__global__ __launch_bounds__(128) void desc_kernel(const float* __restrict__ x) {
    const int g = blockIdx.x, h2 = blockIdx.y, b = blockIdx.z;
    __shared__ float xs[GCD][3][3][58];

    const int tid = threadIdx.x;
    load_taps(x, b, g, h2, xs, tid);
    __syncthreads();

    const int jv0 = h2 % 3, jv1 = (56 + h2) % 3, jv2 = (112 + h2) % 3;
    const unsigned posBase = (unsigned)(b*HD + h2)*WD;

    for (int it = tid; it < GCD * WD; it += 128) {
        int w  = it % WD;
        int gc = it / WD;
        float T[3][3];
        #pragma unroll
        for (int kh = 0; kh < 3; kh++) {
            T[kh][0] = xs[gc][0][kh][w + jv0];
            T[kh][1] = xs[gc][1][kh][w + jv1];
            T[kh][2] = xs[gc][2][kh][w + jv2];
        }
        unsigned f2 = (unsigned)(576 + g*48 + gc*3);
        unsigned f3 = (unsigned)(1344 + g*48 + gc*3);
        #pragma unroll
        for (int kw = 0; kw < 3; kw++) {
            float m = fmaxf(T[0][kw], fmaxf(T[1][kw], T[2][kw]));
            g_desc[(f2 + kw)*POSN + posBase + w] = m;
        }
        #pragma unroll
        for (int kh = 0; kh < 3; kh++) {
            float m = fmaxf(T[kh][0], fmaxf(T[kh][1], T[kh][2]));
            g_desc[(f3 + kh)*POSN + posBase + w] = m;
        }
    }

    const int jvv[3] = {jv0, jv1, jv2};
    for (int it = tid; it < 4 * WD; it += 128) {
        int w  = it % WD;
        int jc = it / WD;
        unsigned f1 = (unsigned)(g*36 + jc*9);
        #pragma unroll
        for (int kh = 0; kh < 3; kh++) {
            #pragma unroll
            for (int kw = 0; kw < 3; kw++) {
                int wp = w + jvv[kw];
                float m = xs[jc][kw][kh][wp];
                m = fmaxf(m, xs[jc + 4 ][kw][kh][wp]);
                m = fmaxf(m, xs[jc + 8 ][kw][kh][wp]);
                m = fmaxf(m, xs[jc + 12][kw][kh][wp]);
                g_desc[(f1 + kh*3 + kw)*POSN + posBase + w] = m;
            }
        }
    }
}

// ---------------------------------------------------------------------------
// K2: GEMM1, now 3xBF16 m16n8k16. BM=64, BN=96, tile = 8 kp (16 k).
// 256 threads = 8 warps (2m x 4n). Partials out (no BN).
// smem: A [8][72] u32 x2 + B [8][104] u32 x2 = ~11 KB.
// ---------------------------------------------------------------------------
#define GBM 64
#define APR 72
#define BPR 104

__global__ __launch_bounds__(256) void gemm_tc_kernel() {
    __shared__ uint32_t Aph[8][APR], Apl[8][APR];
    __shared__ uint32_t Bph[8][BPR], Bpl[8][BPR];

    const int tid  = threadIdx.x;
    const int warp = tid >> 5;
    const int lane = tid & 31;
    const int wm = warp >> 2;          // 0..1 (m)
    const int wn = warp & 3;           // 0..3 (n)
    const int ar = lane >> 2;          // 0..7
    const int ac = lane & 3;           // 0..3
    const unsigned row0 = blockIdx.x * GBM;
    const int khalf = blockIdx.y;
    const unsigned kbase = khalf * KHALF;          // k units
    const unsigned kpbase = kbase >> 1;            // kp units

    float c[2][3][4];
    #pragma unroll
    for (int mt = 0; mt < 2; mt++)
        #pragma unroll
        for (int nt = 0; nt < 3; nt++)
            #pragma unroll
            for (int q = 0; q < 4; q++) c[mt][nt][q] = 0.f;

    const int akp = tid >> 5;          // 0..7 (kp row in tile)
    const int am2 = (lane) * 2;        // 0..62 (m pair)

    for (int k0 = 0; k0 < KHALF; k0 += 16) {
        // A tile: 16 k x 64 m -> bf16x2 k-pairs. Each thread: 2 float2 loads.
        {
            unsigned krow = kbase + k0 + 2*akp;
            float2 v0 = *reinterpret_cast<const float2*>(&g_desc[(size_t)krow*POSN + row0 + am2]);
            float2 v1 = *reinterpret_cast<const float2*>(&g_desc[(size_t)(krow+1)*POSN + row0 + am2]);
            float h00 = bfround(v0.x), h10 = bfround(v1.x);
            float h01 = bfround(v0.y), h11 = bfround(v1.y);
            *reinterpret_cast<uint2*>(&Aph[akp][am2]) =
                make_uint2(packbf(h00, h10), packbf(h01, h11));
            *reinterpret_cast<uint2*>(&Apl[akp][am2]) =
                make_uint2(packbf(v0.x - h00, v1.x - h10),
                           packbf(v0.y - h01, v1.y - h11));
        }
        // B tile: 8 kp x 96 n pre-packed, coalesced (768 u32 per array)
        {
            const unsigned base = (kpbase + (k0 >> 1)) * OUT1;
            #pragma unroll
            for (int i = 0; i < 3; i++) {
                int idx = tid + (i << 8);
                int n = idx % OUT1, kp = idx / OUT1;
                Bph[kp][n] = g_w1ph[base + idx];
                Bpl[kp][n] = g_w1pl[base + idx];
            }
        }
        __syncthreads();

        uint32_t ah[2][4], al[2][4];
        #pragma unroll
        for (int mt = 0; mt < 2; mt++) {
            int mrow = wm*32 + mt*16 + ar;
            ah[mt][0] = Aph[ac  ][mrow];   ah[mt][1] = Aph[ac  ][mrow+8];
            ah[mt][2] = Aph[ac+4][mrow];   ah[mt][3] = Aph[ac+4][mrow+8];
            al[mt][0] = Apl[ac  ][mrow];   al[mt][1] = Apl[ac  ][mrow+8];
            al[mt][2] = Apl[ac+4][mrow];   al[mt][3] = Apl[ac+4][mrow+8];
        }
        uint32_t bh[3][2], bl[3][2];
        #pragma unroll
        for (int nt = 0; nt < 3; nt++) {
            int n = wn*24 + nt*8 + ar;
            bh[nt][0] = Bph[ac][n];  bh[nt][1] = Bph[ac+4][n];
            bl[nt][0] = Bpl[ac][n];  bl[nt][1] = Bpl[ac+4][n];
        }
        #pragma unroll
        for (int mt = 0; mt < 2; mt++)
            #pragma unroll
            for (int nt = 0; nt < 3; nt++) {
                mma_bf16(c[mt][nt], ah[mt], bl[nt]);   // hi x lo
                mma_bf16(c[mt][nt], al[mt], bh[nt]);   // lo x hi
                mma_bf16(c[mt][nt], ah[mt], bh[nt]);   // hi x hi
            }
        __syncthreads();
    }

    float* rp = &g_rp[(size_t)khalf * POSN * OUT1];
    #pragma unroll
    for (int nt = 0; nt < 3; nt++) {
        int n0 = wn*24 + nt*8 + 2*ac;
        #pragma unroll
        for (int mt = 0; mt < 2; mt++) {
            unsigned m0 = row0 + wm*32 + mt*16 + ar;
            *reinterpret_cast<float2*>(&rp[m0*OUT1 + n0]) =
                make_float2(c[mt][nt][0], c[mt][nt][1]);
            *reinterpret_cast<float2*>(&rp[(m0+8)*OUT1 + n0]) =
                make_float2(c[mt][nt][2], c[mt][nt][3]);
        }
    }
}

// ---------------------------------------------------------------------------
// K2b: GEMM2 (tf32x3, unchanged from R10): wab = relu(BN(rp0+rp1)) @ w23 + bias
// ---------------------------------------------------------------------------
#define GBK 16
#define A2STR 72
#define B2STR 200

__global__ __launch_bounds__(256) void gemm2_kernel(
    const float* __restrict__ gamma, const float* __restrict__ beta,
    const float* __restrict__ mean,  const float* __restrict__ var,
    const float* __restrict__ b2,    const float* __restrict__ b3)
{
    __shared__ float A2h[GBK][A2STR], A2l[GBK][A2STR];
    __shared__ float B2h[GBK][B2STR], B2l[GBK][B2STR];
    __shared__ float sS[OUT1], sB[OUT1];

    const int tid  = threadIdx.x;
    const int warp = tid >> 5;
    const int lane = tid & 31;
    const int wm = warp >> 2;
    const int wn = warp & 3;
    const int ar = lane >> 2;
    const int ac = lane & 3;
    const unsigned row0 = blockIdx.x * GBM;

    if (tid < OUT1) {
        float s = gamma[tid] * rsqrtf(var[tid] + 1e-5f);
        sS[tid] = s;
        sB[tid] = beta[tid] - mean[tid] * s;
    }
    __syncthreads();

    float c[2][6][4];
    #pragma unroll
    for (int mt = 0; mt < 2; mt++)
        #pragma unroll
        for (int nt = 0; nt < 6; nt++)
            #pragma unroll
            for (int q = 0; q < 4; q++) c[mt][nt][q] = 0.f;

    const int am = tid >> 2;
    const int akq = tid & 3;

    #pragma unroll
    for (int k0 = 0; k0 < OUT1; k0 += GBK) {
        {
            int kk = k0 + akq*4;
            unsigned base = (row0 + am)*OUT1 + kk;
            float4 p0 = *reinterpret_cast<const float4*>(&g_rp[base]);
            float4 p1 = *reinterpret_cast<const float4*>(&g_rp[(size_t)POSN*OUT1 + base]);
            float v[4] = {p0.x+p1.x, p0.y+p1.y, p0.z+p1.z, p0.w+p1.w};
            #pragma unroll
            for (int i = 0; i < 4; i++) {
                float r = fmaxf(fmaf(v[i], sS[kk+i], sB[kk+i]), 0.f);
                float h = __uint_as_float(f2tf32(r));
                A2h[akq*4 + i][am] = h;
                A2l[akq*4 + i][am] = __uint_as_float(f2tf32(r - h));
            }
        }
        {
            const unsigned base = (unsigned)k0 * N2;
            #pragma unroll
            for (int i = 0; i < 12; i++) {
                int idx = tid + (i << 8);
                int n = idx % N2, k = idx / N2;
                B2h[k][n] = g_w23h[base + idx];
                B2l[k][n] = g_w23l[base + idx];
            }
        }
        __syncthreads();

        #pragma unroll
        for (int ks = 0; ks < 2; ks++) {
            const int kb = ks * 8;
            uint32_t ah[2][4], al[2][4];
            #pragma unroll
            for (int mt = 0; mt < 2; mt++) {
                int mrow = wm*32 + mt*16 + ar;
                ah[mt][0] = __float_as_uint(A2h[kb+ac  ][mrow  ]);
                ah[mt][1] = __float_as_uint(A2h[kb+ac  ][mrow+8]);
                ah[mt][2] = __float_as_uint(A2h[kb+ac+4][mrow  ]);
                ah[mt][3] = __float_as_uint(A2h[kb+ac+4][mrow+8]);
                al[mt][0] = __float_as_uint(A2l[kb+ac  ][mrow  ]);
                al[mt][1] = __float_as_uint(A2l[kb+ac  ][mrow+8]);
                al[mt][2] = __float_as_uint(A2l[kb+ac+4][mrow  ]);
                al[mt][3] = __float_as_uint(A2l[kb+ac+4][mrow+8]);
            }
            uint32_t bh[6][2], bl[6][2];
            #pragma unroll
            for (int nt = 0; nt < 6; nt++) {
                int n = wn*48 + nt*8 + ar;
                bh[nt][0] = __float_as_uint(B2h[kb+ac  ][n]);
                bh[nt][1] = __float_as_uint(B2h[kb+ac+4][n]);
                bl[nt][0] = __float_as_uint(B2l[kb+ac  ][n]);
                bl[nt][1] = __float_as_uint(B2l[kb+ac+4][n]);
            }
            #pragma unroll
            for (int mt = 0; mt < 2; mt++)
                #pragma unroll
                for (int nt = 0; nt < 6; nt++) {
                    mma_tf32(c[mt][nt], ah[mt], bl[nt]);
                    mma_tf32(c[mt][nt], al[mt], bh[nt]);
                    mma_tf32(c[mt][nt], ah[mt], bh[nt]);
                }
        }
        __syncthreads();
    }

    #pragma unroll
    for (int nt = 0; nt < 6; nt++) {
        int n0 = wn*48 + nt*8 + 2*ac;
        float bias0 = (n0 < OUT1) ? b2[n0] : b3[n0 - OUT1];
        float bias1 = (n0 + 1 < OUT1) ? b2[n0 + 1] : b3[n0 + 1 - OUT1];
        #pragma unroll
        for (int mt = 0; mt < 2; mt++) {
            unsigned m0 = row0 + wm*32 + mt*16 + ar;
            *reinterpret_cast<float2*>(&g_wab[(size_t)m0*N2 + n0]) =
                make_float2(c[mt][nt][0] + bias0, c[mt][nt][1] + bias1);
            *reinterpret_cast<float2*>(&g_wab[(size_t)(m0+8)*N2 + n0]) =
                make_float2(c[mt][nt][2] + bias0, c[mt][nt][3] + bias1);
        }
    }
}

// ---------------------------------------------------------------------------
// K3: apply (unchanged from R10)
// ---------------------------------------------------------------------------
__global__ __launch_bounds__(128) void apply_kernel(
    const float* __restrict__ x, float* __restrict__ out)
{
    const int g = blockIdx.x, h2 = blockIdx.y, b = blockIdx.z;
    __shared__ float xs[GCD][3][3][58];
    __shared__ float wab[WD][12];
    __shared__ float sms[WD*37];

    const int tid = threadIdx.x;
    const unsigned posBase = (unsigned)(b*HD + h2)*WD;

    for (int it = tid; it < WD * 12; it += 128) {
        int q = it % 12;
        int w = it / 12;
        int col = (q < 6) ? (g*6 + q) : (OUT1 + g*6 + q - 6);
        wab[w][q] = g_wab[(size_t)(posBase + w)*N2 + col];
    }
    load_taps(x, b, g, h2, xs, tid);
    __syncthreads();

    for (int it = tid; it < WD * 4; it += 128) {
        int t = it % 4;
        int w = it / 4;
        int nh = t >> 1, nw = t & 1;
        float e[9], m = -1e30f;
        #pragma unroll
        for (int kk = 0; kk < 9; kk++) {
            int kh = kk / 3, kw = kk % 3;
            e[kk] = wab[w][kh*2 + nh] * wab[w][6 + kw*2 + nw];
            m = fmaxf(m, e[kk]);
        }
        float s = 0.f;
        #pragma unroll
        for (int kk = 0; kk < 9; kk++) { e[kk] = expf(e[kk] - m); s += e[kk]; }
        float inv = 1.f / (s * 9.f);
        #pragma unroll
        for (int kk = 0; kk < 9; kk++) sms[w*37 + t*9 + kk] = e[kk] * inv;
    }
    __syncthreads();

    const int jv0 = h2 % 3, jv1 = (56 + h2) % 3, jv2 = (112 + h2) % 3;
    const int jvv[3] = {jv0, jv1, jv2};

    for (int it = tid; it < GCD * WD; it += 128) {
        int w  = it % WD;
        int gc = it / WD;
        float o[4] = {0.f, 0.f, 0.f, 0.f};
        #pragma unroll
        for (int kk = 0; kk < 9; kk++) {
            int kh = kk / 3, kw = kk % 3;
            float u = xs[gc][kw][kh][w + jvv[kw]];
            #pragma unroll
            for (int t = 0; t < 4; t++)
                o[t] = fmaf(u, sms[w*37 + t*9 + kk], o[t]);
        }
        int c = g*GCD + gc;
        #pragma unroll
        for (int t = 0; t < 4; t++) {
            int nh = t >> 1, nw = t & 1;
            out[(((unsigned)(b*CD + c))*OWD + 2*h2 + nh)*OWD + 2*w + nw] = o[t];
        }
    }
}

// ---------------------------------------------------------------------------
extern "C" void kernel_launch(void* const* d_in, const int* in_sizes, int n_in,
                              void* d_out, int out_size) {
    const float* x     = (const float*)d_in[0];
    const float* w1    = (const float*)d_in[1];
    const float* gamma = (const float*)d_in[2];
    const float* beta  = (const float*)d_in[3];
    const float* mean  = (const float*)d_in[4];
    const float* var   = (const float*)d_in[5];
    const float* w2    = (const float*)d_in[6];
    const float* b2    = (const float*)d_in[7];
    const float* w3    = (const float*)d_in[8];
    const float* b3    = (const float*)d_in[9];
    float* out = (float*)d_out;

    dim3 gridA(GD, HD, BD);   // (16, 56, 4)
    w1pack_kernel<<<((IN1/2)*OUT1 + 255)/256, 256>>>(w1);
    w23split_kernel<<<(OUT1*N2 + 255)/256, 256>>>(w2, w3);
    desc_kernel<<<gridA, 128>>>(x);
    gemm_tc_kernel<<<dim3(POSN / GBM, 2), 256>>>();
    gemm2_kernel<<<POSN / GBM, 256>>>(gamma, beta, mean, var, b2, b3);
    apply_kernel<<<gridA, 128>>>(x, out);
}